// round 16
// baseline (speedup 1.0000x reference)
#include <cuda_runtime.h>
#include <cuda_fp16.h>
#include <math.h>
#include <stdint.h>

#define QLEN   1024
#define BSZ    4
#define DMODEL 1024
#define NHEAD  16
#define DHEAD  64
#define DINNER 4096
#define MEMLEN 1024
#define KLEN   2048
#define H3     (3 * DMODEL)   // 3072

// ---- static device scratch (no cudaMalloc allowed) ----
__device__ __half g_heads16[(size_t)KLEN * BSZ * H3];        // fp16 QKV heads
__device__ __half g_rk16[(size_t)KLEN * DMODEL];             // fp16 rk
__device__ float  g_rbias[(size_t)NHEAD * KLEN];
__device__ __half g_BD[(size_t)BSZ * NHEAD * QLEN * KLEN];   // j-indexed BDr
__device__ __half g_av16[(size_t)QLEN * BSZ * DMODEL];
__device__ float  g_tmp[(size_t)QLEN * BSZ * DMODEL];
__device__ float  g_out1[(size_t)QLEN * BSZ * DMODEL];
__device__ __half g_out116[(size_t)QLEN * BSZ * DMODEL];
__device__ __half g_ffh16[(size_t)QLEN * BSZ * DINNER];
__device__ __half g_cat16[(size_t)KLEN * BSZ * DMODEL];
__device__ __half g_r16[(size_t)KLEN * DMODEL];
__device__ __half g_qkvw16[(size_t)DMODEL * H3];
__device__ __half g_rnw16[(size_t)DMODEL * DMODEL];
__device__ __half g_ow16[(size_t)DMODEL * DMODEL];
__device__ __half g_ffw116[(size_t)DMODEL * DINNER];
__device__ __half g_ffw216[(size_t)DINNER * DMODEL];

__device__ __forceinline__ void cpa16(uint32_t s, const void* g) {
    asm volatile("cp.async.cg.shared.global [%0], [%1], 16;" :: "r"(s), "l"(g));
}
#define CP_COMMIT() asm volatile("cp.async.commit_group;")
#define CP_WAIT(N)  asm volatile("cp.async.wait_group %0;" :: "n"(N))

#define MMA_F16(acc, av, bv)                                                \
    asm volatile(                                                           \
        "mma.sync.aligned.m16n8k16.row.col.f32.f16.f16.f32 "                \
        "{%0,%1,%2,%3}, {%4,%5,%6,%7}, {%8,%9}, {%0,%1,%2,%3};"             \
        : "+f"(acc[0]), "+f"(acc[1]), "+f"(acc[2]), "+f"(acc[3])            \
        : "r"(av[0]), "r"(av[1]), "r"(av[2]), "r"(av[3]),                   \
          "r"(bv[0]), "r"(bv[1]))

#define LDSM_X4(r0, r1, r2, r3, addr)                                       \
    asm volatile("ldmatrix.sync.aligned.m8n8.x4.shared.b16 {%0,%1,%2,%3}, [%4];" \
        : "=r"(r0), "=r"(r1), "=r"(r2), "=r"(r3) : "r"(addr))
#define LDSM_X4T(r0, r1, r2, r3, addr)                                      \
    asm volatile("ldmatrix.sync.aligned.m8n8.x4.trans.shared.b16 {%0,%1,%2,%3}, [%4];" \
        : "=r"(r0), "=r"(r1), "=r"(r2), "=r"(r3) : "r"(addr))

// ----------------------------------------------------------------------------
__global__ __launch_bounds__(256) void cvt_k(
    const float* __restrict__ src, __half* __restrict__ dst)
{
    const int i = (blockIdx.x * 256 + threadIdx.x) * 8;
    const float4 a = *(const float4*)(src + i);
    const float4 b = *(const float4*)(src + i + 4);
    __half2 h[4];
    h[0] = __floats2half2_rn(a.x, a.y);
    h[1] = __floats2half2_rn(a.z, a.w);
    h[2] = __floats2half2_rn(b.x, b.y);
    h[3] = __floats2half2_rn(b.z, b.w);
    *(uint4*)(dst + i) = *(uint4*)h;
}

// ----------------------------------------------------------------------------
// Dense fp16 GEMM with separate B/C strides (ldb/ldc, in elements).
// HOUT=0: fp32 out. HOUT=1: fp16 out.
// ----------------------------------------------------------------------------
#define ASTR 40
#define BSTR 136

template <int HOUT>
__global__ __launch_bounds__(256, 2) void gemm_h(
    const __half* __restrict__ A, int lda,
    const __half* __restrict__ B, int ldb,
    const float* __restrict__ bias, const float* __restrict__ resid, int doRelu,
    void* __restrict__ Cv, __half* __restrict__ C16, int ldc,
    int M, int N, int Kd)
{
    __shared__ __half As[3][128 * ASTR];
    __shared__ __half Bs[3][32 * BSTR];

    const int tid  = threadIdx.x;
    const int warp = tid >> 5, lane = tid & 31;
    const int lr = lane >> 2, lc = lane & 3;
    const int bm = blockIdx.y * 128, bn = blockIdx.x * 128;
    const int wm = (warp & 1) * 64;
    const int wn = (warp >> 1) * 32;

    float acc[4][4][4];
#pragma unroll
    for (int mt = 0; mt < 4; mt++)
#pragma unroll
        for (int nt = 0; nt < 4; nt++)
#pragma unroll
            for (int q = 0; q < 4; q++) acc[mt][nt][q] = 0.f;

    const __half* aPtr[2];
    const __half* bPtr[2];
    uint32_t aDst[2], bDst[2];
#pragma unroll
    for (int h = 0; h < 2; h++) {
        const int ch = tid + h * 256;
        const int ar = ch >> 2, ao = (ch & 3) * 8;
        aPtr[h] = A + (long long)(bm + ar) * lda + ao;
        aDst[h] = (uint32_t)__cvta_generic_to_shared(&As[0][ar * ASTR + ao]);
        const int br = ch >> 4, bo = (ch & 15) * 8;
        bPtr[h] = B + (long long)br * ldb + bn + bo;
        bDst[h] = (uint32_t)__cvta_generic_to_shared(&Bs[0][br * BSTR + bo]);
    }
    const long long bStep = (long long)32 * ldb;

    auto load = [&](int kt, int s) {
#pragma unroll
        for (int h = 0; h < 2; h++)
            cpa16(aDst[h] + s * 128 * ASTR * 2, aPtr[h] + kt * 32);
#pragma unroll
        for (int h = 0; h < 2; h++)
            cpa16(bDst[h] + s * 32 * BSTR * 2, bPtr[h] + kt * bStep);
    };

    const int aRow = lane & 15;
    const int selOff = (lane >> 4) << 3;
    const uint32_t asBase = (uint32_t)__cvta_generic_to_shared(&As[0][0]);
    const uint32_t bsBase = (uint32_t)__cvta_generic_to_shared(&Bs[0][0]);

    const int nk = Kd >> 5;
    load(0, 0); CP_COMMIT();
    load(1, 1); CP_COMMIT();

    for (int kt = 0; kt < nk; kt++) {
        const int s = kt % 3;
        CP_WAIT(1);
        __syncthreads();
        if (kt + 2 < nk) load(kt + 2, (kt + 2) % 3);
        CP_COMMIT();

        const uint32_t aS = asBase + (uint32_t)(s * 128 * ASTR * 2);
        const uint32_t bS = bsBase + (uint32_t)(s * 32 * BSTR * 2);
#pragma unroll
        for (int kk = 0; kk < 32; kk += 16) {
            uint32_t af[4][4], bf[4][2];
#pragma unroll
            for (int mt = 0; mt < 4; mt++) {
                const uint32_t addr = aS +
                    (uint32_t)(((wm + mt * 16 + aRow) * ASTR + kk + selOff) * 2);
                LDSM_X4(af[mt][0], af[mt][1], af[mt][2], af[mt][3], addr);
            }
#pragma unroll
            for (int ntp = 0; ntp < 2; ntp++) {
                const uint32_t addr = bS +
                    (uint32_t)(((kk + aRow) * BSTR + wn + ntp * 16 + selOff) * 2);
                LDSM_X4T(bf[2 * ntp][0], bf[2 * ntp][1],
                         bf[2 * ntp + 1][0], bf[2 * ntp + 1][1], addr);
            }
#pragma unroll
            for (int mt = 0; mt < 4; mt++)
#pragma unroll
                for (int nt = 0; nt < 4; nt++)
                    MMA_F16(acc[mt][nt], af[mt], bf[nt]);
        }
    }

#pragma unroll
    for (int mt = 0; mt < 4; mt++) {
#pragma unroll
        for (int nt = 0; nt < 4; nt++) {
            const int col = bn + wn + nt * 8 + lc * 2;
#pragma unroll
            for (int half = 0; half < 2; half++) {
                const int row = bm + wm + mt * 16 + lr + half * 8;
                float v0 = acc[mt][nt][half * 2 + 0];
                float v1 = acc[mt][nt][half * 2 + 1];
                if (bias) { v0 += bias[col]; v1 += bias[col + 1]; }
                if (resid) {
                    const float* rp = resid + (long long)row * ldc + col;
                    v0 += rp[0]; v1 += rp[1];
                }
                if (doRelu) { v0 = fmaxf(v0, 0.f); v1 = fmaxf(v1, 0.f); }
                if (HOUT == 1) {
                    *(__half2*)((__half*)Cv + (long long)row * ldc + col) =
                        __floats2half2_rn(v0, v1);
                } else {
                    float* cp = (float*)Cv + (long long)row * ldc + col;
                    cp[0] = v0; cp[1] = v1;
                }
            }
        }
    }
}

// ----------------------------------------------------------------------------
// rbias[n][c] = rrb_n . rk16_c  (fp32 accumulate over fp16 rk)
// ----------------------------------------------------------------------------
__global__ __launch_bounds__(256) void rbias_k(
    const float* __restrict__ rrb, const __half* __restrict__ rk16,
    float* __restrict__ rbias)
{
    const int idx = blockIdx.x * 256 + threadIdx.x;
    const int c = idx >> 4, n = idx & 15;
    const __half2* rp = (const __half2*)(rk16 + (size_t)c * DMODEL + n * DHEAD);
    const float* bp = rrb + n * DHEAD;
    float s = 0.f;
#pragma unroll
    for (int d = 0; d < 32; d++) {
        const float2 rv = __half22float2(rp[d]);
        s += rv.x * bp[2 * d] + rv.y * bp[2 * d + 1];
    }
    rbias[n * KLEN + c] = s;
}

// ----------------------------------------------------------------------------
// BD GEMM fp16, j-indexed output: BDr[bn][i][j] = q_i . rk_{j-i+1023} + rbias.
// ----------------------------------------------------------------------------
#define BDSTR 72

__global__ __launch_bounds__(256, 2) void bd16_gemm(
    const __half* __restrict__ Q16,
    const __half* __restrict__ RK16,
    const float* __restrict__ rbias, __half* __restrict__ BD)
{
    __shared__ __half As[128 * BDSTR];
    __shared__ __half Bs[128 * BDSTR];

    const int tid = threadIdx.x;
    const int warp = tid >> 5, lane = tid & 31;
    const int lr = lane >> 2, lc = lane & 3;
    const int bm = blockIdx.y * 128, bn = blockIdx.x * 128;
    if (bm + bn < 769) return;   // whole tile lands at j < 0, never read
    const int bnidx = blockIdx.z;
    const int b = bnidx >> 4, n = bnidx & 15;
    const int wm = (warp & 1) * 64;
    const int wn = (warp >> 1) * 32;
    const int aRow = lane & 15;
    const int selOff = (lane >> 4) << 3;
    const uint32_t as_b = (uint32_t)__cvta_generic_to_shared(As);
    const uint32_t bs_b = (uint32_t)__cvta_generic_to_shared(Bs);

#pragma unroll
    for (int h = 0; h < 4; h++) {
        const int ch = tid + h * 256;
        const int row = ch >> 3, seg = (ch & 7) * 8;
        const __half* ga = Q16 + ((size_t)(bm + row) * BSZ + b) * H3 + n * DHEAD + seg;
        cpa16(as_b + (uint32_t)((row * BDSTR + seg) << 1), ga);
    }
#pragma unroll
    for (int h = 0; h < 4; h++) {
        const int ch = tid + h * 256;
        const int row = ch >> 3, seg = (ch & 7) * 8;
        const __half* gb = RK16 + (size_t)(bn + row) * DMODEL + n * DHEAD + seg;
        cpa16(bs_b + (uint32_t)((row * BDSTR + seg) << 1), gb);
    }
    CP_COMMIT();

    float acc[4][4][4];
#pragma unroll
    for (int mt = 0; mt < 4; mt++)
#pragma unroll
        for (int nt = 0; nt < 4; nt++)
#pragma unroll
            for (int q = 0; q < 4; q++) acc[mt][nt][q] = 0.f;

    CP_WAIT(0);
    __syncthreads();

#pragma unroll
    for (int kk = 0; kk < 64; kk += 16) {
        uint32_t af[4][4], bfr[4][2];
#pragma unroll
        for (int mt = 0; mt < 4; mt++) {
            const uint32_t addr = as_b +
                (uint32_t)(((wm + mt * 16 + aRow) * BDSTR + kk + selOff) << 1);
            LDSM_X4(af[mt][0], af[mt][1], af[mt][2], af[mt][3], addr);
        }
#pragma unroll
        for (int p = 0; p < 2; p++) {
            uint32_t r0, r1, r2, r3;
            const uint32_t addr = bs_b +
                (uint32_t)(((wn + p * 16 + aRow) * BDSTR + kk + selOff) << 1);
            LDSM_X4(r0, r1, r2, r3, addr);
            bfr[2 * p][0] = r0; bfr[2 * p][1] = r2;
            bfr[2 * p + 1][0] = r1; bfr[2 * p + 1][1] = r3;
        }
#pragma unroll
        for (int mt = 0; mt < 4; mt++)
#pragma unroll
            for (int nt = 0; nt < 4; nt++)
                MMA_F16(acc[mt][nt], af[mt], bfr[nt]);
    }

    // epilogue: + rbias, rel-shifted fp16 store (j = c + i - 1023)
#pragma unroll
    for (int mt = 0; mt < 4; mt++) {
#pragma unroll
        for (int nt = 0; nt < 4; nt++) {
            const int col = bn + wn + nt * 8 + lc * 2;
            const float rb0 = rbias[n * KLEN + col];
            const float rb1 = rbias[n * KLEN + col + 1];
#pragma unroll
            for (int half = 0; half < 2; half++) {
                const int row = bm + wm + mt * 16 + lr + half * 8;
                const float v0 = acc[mt][nt][half * 2 + 0] + rb0;
                const float v1 = acc[mt][nt][half * 2 + 1] + rb1;
                __half* rowp = BD + ((size_t)bnidx * QLEN + row) * KLEN;
                const int j = col + row - (QLEN - 1);
                if (j >= 0)     rowp[j]     = __float2half_rn(v0);
                if (j + 1 >= 0) rowp[j + 1] = __float2half_rn(v1);
            }
        }
    }
}

// ----------------------------------------------------------------------------
// Flash attention (proven v6): 64-row q-tiles, 256 threads, 2 CTAs/SM.
// ----------------------------------------------------------------------------
#define KSTR  72
#define BDF   136
#define OSTR  72
#define FLASH_SMEM (64*KSTR*2 /*Q*/ + 2*128*KSTR*2 /*K*/ + 128*KSTR*2 /*V*/ \
                    + 64*BDF*2 /*Bd*/ + 2*64*4 /*pmax*/ + 2*64*4 /*psum*/)

__global__ __launch_bounds__(256, 2) void flash_k(
    const __half* __restrict__ heads16,
    const __half* __restrict__ BD,
    const float* __restrict__ rwb, __half* __restrict__ av16)
{
    extern __shared__ char smc[];
    __half* Qs16 = (__half*)smc;
    __half* Ks16 = Qs16 + 64 * KSTR;
    __half* Vs16 = Ks16 + 2 * 128 * KSTR;
    __half* Bds  = Vs16 + 128 * KSTR;
    float*  pmax = (float*)(Bds + 64 * BDF);
    float*  psum = pmax + 2 * 64;
    float*  Osum = (float*)Ks16;
    const uint32_t qs_b = (uint32_t)__cvta_generic_to_shared(Qs16);
    const uint32_t ks_b = (uint32_t)__cvta_generic_to_shared(Ks16);
    const uint32_t vs_b = (uint32_t)__cvta_generic_to_shared(Vs16);
    const uint32_t bd_b = (uint32_t)__cvta_generic_to_shared(Bds);

    const int tid = threadIdx.x;
    const int warp = tid >> 5, lane = tid & 31;
    const int lr = lane >> 2, lc = lane & 3;
    const int aRow = lane & 15;
    const int selOff = (lane >> 4) << 3;
    const int qt = (int)gridDim.x - 1 - (int)blockIdx.x;   // longest-first
    const int i0 = qt * 64;
    const int bn = blockIdx.y;
    const int b = bn >> 4, n = bn & 15;
    const int rg  = warp & 3;
    const int chh = warp >> 2;
    const int wm  = rg * 16;
    const int njt = ((i0 + 63 + MEMLEN) >> 7) + 1;

    auto loadK = [&](int jt, int buf) {
        const int j0 = jt * 128;
#pragma unroll
        for (int it = 0; it < 4; it++) {
            const int c = tid + it * 256;
            const int row = c >> 3, seg = (c & 7) << 3;
            const __half* g = heads16 + ((size_t)(j0 + row) * BSZ + b) * H3 + DMODEL + n * DHEAD + seg;
            cpa16(ks_b + (uint32_t)((((buf << 7) + row) * KSTR + seg) << 1), g);
        }
    };
    auto loadV = [&](int jt) {
        const int j0 = jt * 128;
#pragma unroll
        for (int it = 0; it < 4; it++) {
            const int c = tid + it * 256;
            const int row = c >> 3, seg = (c & 7) << 3;
            const __half* g = heads16 + ((size_t)(j0 + row) * BSZ + b) * H3 + 2 * DMODEL + n * DHEAD + seg;
            cpa16(vs_b + (uint32_t)((row * KSTR + seg) << 1), g);
        }
    };
    auto loadBd = [&](int jt) {
        const int j0 = jt * 128;
#pragma unroll
        for (int it = 0; it < 4; it++) {
            const int c = tid + it * 256;
            const int row = c >> 4, seg = (c & 15) << 3;
            const __half* g = BD + ((size_t)bn * QLEN + i0 + row) * KLEN + j0 + seg;
            cpa16(bd_b + (uint32_t)((row * BDF + seg) << 1), g);
        }
    };

    loadK(0, 0); CP_COMMIT();
    const __half* qb16 = heads16 + (size_t)MEMLEN * BSZ * H3;
#pragma unroll
    for (int it = 0; it < 4; it++) {
        const int idx = tid + it * 256;
        const int row = idx >> 4, c4 = (idx & 15) * 4;
        const __half2* qp = (const __half2*)(qb16 + ((size_t)(i0 + row) * BSZ + b) * H3 + n * DHEAD + c4);
        const float2 q0 = __half22float2(qp[0]);
        const float2 q1 = __half22float2(qp[1]);
        const float4 bb = *(const float4*)(rwb + n * DHEAD + c4);
        *(__half2*)(Qs16 + row * KSTR + c4)     = __floats2half2_rn(q0.x + bb.x, q0.y + bb.y);
        *(__half2*)(Qs16 + row * KSTR + c4 + 2) = __floats2half2_rn(q1.x + bb.z, q1.y + bb.w);
    }

    float m0 = -1e30f, m1 = -1e30f, l0 = 0.f, l1 = 0.f;

    float accO[8][4];
#pragma unroll
    for (int nt = 0; nt < 8; nt++)
#pragma unroll
        for (int q = 0; q < 4; q++) accO[nt][q] = 0.f;

    CP_WAIT(0);
    __syncthreads();

    for (int jt = 0; jt < njt; jt++) {
        const int j0 = jt * 128;
        const int cur = jt & 1;
        const bool more = (jt + 1 < njt);

        loadV(jt); loadBd(jt); CP_COMMIT();
        if (more) { loadK(jt + 1, cur ^ 1); CP_COMMIT(); }

        float accS[8][4];
#pragma unroll
        for (int nt = 0; nt < 8; nt++)
#pragma unroll
            for (int q = 0; q < 4; q++) accS[nt][q] = 0.f;

#pragma unroll
        for (int kk = 0; kk < 64; kk += 16) {
            uint32_t af[4], bfr[8][2];
            {
                const uint32_t addr = qs_b +
                    (uint32_t)(((wm + aRow) * KSTR + kk + selOff) << 1);
                LDSM_X4(af[0], af[1], af[2], af[3], addr);
            }
#pragma unroll
            for (int p = 0; p < 4; p++) {
                uint32_t r0, r1, r2, r3;
                const uint32_t addr = ks_b +
                    (uint32_t)((((cur << 7) + chh * 64 + p * 16 + aRow) * KSTR + kk + selOff) << 1);
                LDSM_X4(r0, r1, r2, r3, addr);
                bfr[2 * p][0] = r0; bfr[2 * p][1] = r2;
                bfr[2 * p + 1][0] = r1; bfr[2 * p + 1][1] = r3;
            }
#pragma unroll
            for (int nt = 0; nt < 8; nt++)
                MMA_F16(accS[nt], af, bfr[nt]);
        }

        if (more) { CP_WAIT(1); } else { CP_WAIT(0); }
        __syncthreads();

        const int dcol = j0 + chh * 64 - (i0 + wm);
        const int lim0 = lr + MEMLEN - dcol;
        const int lim1 = lim0 + 8;
        float mx0 = -1e30f, mx1 = -1e30f;
#pragma unroll
        for (int nt = 0; nt < 8; nt++) {
            const int cl = nt * 8 + 2 * lc;
            const float2 b0 = __half22float2(*(const __half2*)&Bds[(wm + lr) * BDF + chh * 64 + nt * 8 + 2 * lc]);
            const float2 b1 = __half22float2(*(const __half2*)&Bds[(wm + lr + 8) * BDF + chh * 64 + nt * 8 + 2 * lc]);
            accS[nt][0] = (cl     <= lim0) ? (accS[nt][0] + b0.x) * 0.125f : -1e30f;
            accS[nt][1] = (cl + 1 <= lim0) ? (accS[nt][1] + b0.y) * 0.125f : -1e30f;
            accS[nt][2] = (cl     <= lim1) ? (accS[nt][2] + b1.x) * 0.125f : -1e30f;
            accS[nt][3] = (cl + 1 <= lim1) ? (accS[nt][3] + b1.y) * 0.125f : -1e30f;
            mx0 = fmaxf(mx0, fmaxf(accS[nt][0], accS[nt][1]));
            mx1 = fmaxf(mx1, fmaxf(accS[nt][2], accS[nt][3]));
        }
#pragma unroll
        for (int o = 1; o <= 2; o <<= 1) {
            mx0 = fmaxf(mx0, __shfl_xor_sync(0xffffffffu, mx0, o));
            mx1 = fmaxf(mx1, __shfl_xor_sync(0xffffffffu, mx1, o));
        }
        if (lc == 0) {
            pmax[chh * 64 + wm + lr] = mx0;
            pmax[chh * 64 + wm + lr + 8] = mx1;
        }
        __syncthreads();

        const float nm0 = fmaxf(m0, fmaxf(pmax[wm + lr], pmax[64 + wm + lr]));
        const float nm1 = fmaxf(m1, fmaxf(pmax[wm + lr + 8], pmax[64 + wm + lr + 8]));

        uint32_t pLo[8], pHi[8];
        float ls0 = 0.f, ls1 = 0.f;
#pragma unroll
        for (int nt = 0; nt < 8; nt++) {
            const __half2 h0 = __floats2half2_rn(__expf(accS[nt][0] - nm0),
                                                 __expf(accS[nt][1] - nm0));
            const __half2 h1 = __floats2half2_rn(__expf(accS[nt][2] - nm1),
                                                 __expf(accS[nt][3] - nm1));
            pLo[nt] = *(const uint32_t*)&h0;
            pHi[nt] = *(const uint32_t*)&h1;
            const float2 f0 = __half22float2(h0);
            const float2 f1 = __half22float2(h1);
            ls0 += f0.x + f0.y;
            ls1 += f1.x + f1.y;
        }
#pragma unroll
        for (int o = 1; o <= 2; o <<= 1) {
            ls0 += __shfl_xor_sync(0xffffffffu, ls0, o);
            ls1 += __shfl_xor_sync(0xffffffffu, ls1, o);
        }
        if (lc == 0) {
            psum[chh * 64 + wm + lr] = ls0;
            psum[chh * 64 + wm + lr + 8] = ls1;
        }
        __syncthreads();

        const float lt0 = psum[wm + lr] + psum[64 + wm + lr];
        const float lt1 = psum[wm + lr + 8] + psum[64 + wm + lr + 8];
        const float a0 = __expf(m0 - nm0);
        const float a1 = __expf(m1 - nm1);
        m0 = nm0; m1 = nm1;
        l0 = l0 * a0 + lt0;
        l1 = l1 * a1 + lt1;

#pragma unroll
        for (int nt = 0; nt < 8; nt++) {
            accO[nt][0] *= a0; accO[nt][1] *= a0;
            accO[nt][2] *= a1; accO[nt][3] *= a1;
        }
#pragma unroll
        for (int p = 0; p < 4; p++) {
            uint32_t af[4];
            af[0] = pLo[2 * p];     af[1] = pHi[2 * p];
            af[2] = pLo[2 * p + 1]; af[3] = pHi[2 * p + 1];
            uint32_t bf[8][2];
#pragma unroll
            for (int nb = 0; nb < 4; nb++) {
                const uint32_t addr = vs_b +
                    (uint32_t)(((chh * 64 + p * 16 + aRow) * KSTR + nb * 16 + selOff) << 1);
                LDSM_X4T(bf[2 * nb][0], bf[2 * nb][1],
                         bf[2 * nb + 1][0], bf[2 * nb + 1][1], addr);
            }
#pragma unroll
            for (int nt = 0; nt < 8; nt++)
                MMA_F16(accO[nt], af, bf[nt]);
        }

        if (more) CP_WAIT(0);
        __syncthreads();
    }

    if (chh == 1) {
#pragma unroll
        for (int nt = 0; nt < 8; nt++) {
            const int col = nt * 8 + 2 * lc;
            *(float2*)&Osum[(wm + lr) * OSTR + col] =
                make_float2(accO[nt][0], accO[nt][1]);
            *(float2*)&Osum[(wm + lr + 8) * OSTR + col] =
                make_float2(accO[nt][2], accO[nt][3]);
        }
    }
    __syncthreads();
    if (chh == 0) {
        const float inv0 = 1.f / l0;
        const float inv1 = 1.f / l1;
#pragma unroll
        for (int nt = 0; nt < 8; nt++) {
            const int col = nt * 8 + 2 * lc;
            const float2 s0 = *(const float2*)&Osum[(wm + lr) * OSTR + col];
            const float2 s1 = *(const float2*)&Osum[(wm + lr + 8) * OSTR + col];
            __half2* p0 = (__half2*)(av16 + ((size_t)(i0 + wm + lr) * BSZ + b) * DMODEL + n * DHEAD + col);
            *p0 = __floats2half2_rn((accO[nt][0] + s0.x) * inv0,
                                    (accO[nt][1] + s0.y) * inv0);
            __half2* p1 = (__half2*)(av16 + ((size_t)(i0 + wm + lr + 8) * BSZ + b) * DMODEL + n * DHEAD + col);
            *p1 = __floats2half2_rn((accO[nt][2] + s1.x) * inv1,
                                    (accO[nt][3] + s1.y) * inv1);
        }
    }
}

// ----------------------------------------------------------------------------
__device__ __forceinline__ float warpSum(float v) {
#pragma unroll
    for (int o = 16; o; o >>= 1) v += __shfl_xor_sync(0xffffffffu, v, o);
    return v;
}

__global__ __launch_bounds__(256) void ln_k(
    const float* __restrict__ X, const float* __restrict__ gam,
    const float* __restrict__ bet, float* __restrict__ Y,
    __half* __restrict__ Y16)
{
    __shared__ float red[8];
    const size_t row = blockIdx.x;
    const int tid = threadIdx.x;
    const float4 v = *(const float4*)(X + row * DMODEL + tid * 4);
    float s = v.x + v.y + v.z + v.w;
    float q = v.x * v.x + v.y * v.y + v.z * v.z + v.w * v.w;

    float ws = warpSum(s);
    if ((tid & 31) == 0) red[tid >> 5] = ws;
    __syncthreads();
    if (tid < 32) {
        float t = (tid < 8) ? red[tid] : 0.f;
        t = warpSum(t);
        if (tid == 0) red[0] = t;
    }
    __syncthreads();
    const float mu = red[0] * (1.f / DMODEL);
    __syncthreads();

    float wq = warpSum(q);
    if ((tid & 31) == 0) red[tid >> 5] = wq;
    __syncthreads();
    if (tid < 32) {
        float t = (tid < 8) ? red[tid] : 0.f;
        t = warpSum(t);
        if (tid == 0) red[0] = t;
    }
    __syncthreads();
    const float var = red[0] * (1.f / DMODEL) - mu * mu;
    const float rs = rsqrtf(var + 1e-5f);

    const float4 gv = *(const float4*)(gam + tid * 4);
    const float4 bv = *(const float4*)(bet + tid * 4);
    float4 o;
    o.x = (v.x - mu) * rs * gv.x + bv.x;
    o.y = (v.y - mu) * rs * gv.y + bv.y;
    o.z = (v.z - mu) * rs * gv.z + bv.z;
    o.w = (v.w - mu) * rs * gv.w + bv.w;
    *(float4*)(Y + row * DMODEL + tid * 4) = o;
    if (Y16) {
        __half2 h[2] = { __floats2half2_rn(o.x, o.y), __floats2half2_rn(o.z, o.w) };
        *(uint2*)(Y16 + row * DMODEL + tid * 4) = *(uint2*)h;
    }
}

// ----------------------------------------------------------------------------
extern "C" void kernel_launch(void* const* d_in, const int* in_sizes, int n_in,
                              void* d_out, int out_size)
{
    (void)in_sizes; (void)n_in; (void)out_size;
    const float* w       = (const float*)d_in[0];
    const float* r       = (const float*)d_in[1];
    const float* mems    = (const float*)d_in[2];
    const float* qkv_w   = (const float*)d_in[3];
    const float* r_net_w = (const float*)d_in[4];
    const float* o_w     = (const float*)d_in[5];
    const float* rwb     = (const float*)d_in[6];
    const float* rrb     = (const float*)d_in[7];
    const float* ln1g    = (const float*)d_in[8];
    const float* ln1b    = (const float*)d_in[9];
    const float* ffw1    = (const float*)d_in[10];
    const float* ffb1    = (const float*)d_in[11];
    const float* ffw2    = (const float*)d_in[12];
    const float* ffb2    = (const float*)d_in[13];
    const float* ln2g    = (const float*)d_in[14];
    const float* ln2b    = (const float*)d_in[15];
    float* out = (float*)d_out;

    float *rbias, *tmp, *out1;
    __half *heads16, *rk16, *BD, *av16, *out116, *ffh16;
    __half *cat16, *r16, *qkvw16, *rnw16, *ow16, *ffw116, *ffw216;
    cudaGetSymbolAddress((void**)&heads16, g_heads16);
    cudaGetSymbolAddress((void**)&rk16,    g_rk16);
    cudaGetSymbolAddress((void**)&rbias,   g_rbias);
    cudaGetSymbolAddress((void**)&BD,      g_BD);
    cudaGetSymbolAddress((void**)&av16,    g_av16);
    cudaGetSymbolAddress((void**)&tmp,     g_tmp);
    cudaGetSymbolAddress((void**)&out1,    g_out1);
    cudaGetSymbolAddress((void**)&out116,  g_out116);
    cudaGetSymbolAddress((void**)&ffh16,   g_ffh16);
    cudaGetSymbolAddress((void**)&cat16,   g_cat16);
    cudaGetSymbolAddress((void**)&r16,     g_r16);
    cudaGetSymbolAddress((void**)&qkvw16,  g_qkvw16);
    cudaGetSymbolAddress((void**)&rnw16,   g_rnw16);
    cudaGetSymbolAddress((void**)&ow16,    g_ow16);
    cudaGetSymbolAddress((void**)&ffw116,  g_ffw116);
    cudaGetSymbolAddress((void**)&ffw216,  g_ffw216);

    static cudaStream_t s1 = nullptr;
    static cudaEvent_t evFork = nullptr, evQ = nullptr, evCat = nullptr,
                       evJoin = nullptr;
    static int s_init_done = 0;
    if (!s_init_done) {
        cudaFuncSetAttribute(flash_k, cudaFuncAttributeMaxDynamicSharedMemorySize,
                             FLASH_SMEM);
        cudaStreamCreateWithFlags(&s1, cudaStreamNonBlocking);
        cudaEventCreateWithFlags(&evFork, cudaEventDisableTiming);
        cudaEventCreateWithFlags(&evQ, cudaEventDisableTiming);
        cudaEventCreateWithFlags(&evCat, cudaEventDisableTiming);
        cudaEventCreateWithFlags(&evJoin, cudaEventDisableTiming);
        s_init_done = 1;
    }

    const dim3 blk(256);
    const __half* qb16 = heads16 + (size_t)MEMLEN * BSZ * H3;  // query rows
    const size_t halfM = (size_t)(KLEN * BSZ / 2);             // 4096 rows

    // ---- fork side stream ----
    cudaEventRecord(evFork, 0);
    cudaStreamWaitEvent(s1, evFork, 0);

    // side stream: r/weight conversions -> rk GEMM -> rbias
    cvt_k<<<(KLEN * DMODEL) / 2048, blk, 0, s1>>>(r, r16);
    cvt_k<<<(DMODEL * DMODEL) / 2048, blk, 0, s1>>>(r_net_w, rnw16);
    cvt_k<<<(DMODEL * DMODEL) / 2048, blk, 0, s1>>>(o_w, ow16);
    cvt_k<<<(DMODEL * DINNER) / 2048, blk, 0, s1>>>(ffw1, ffw116);
    cvt_k<<<(DINNER * DMODEL) / 2048, blk, 0, s1>>>(ffw2, ffw216);
    gemm_h<1><<<dim3(DMODEL / 128, KLEN / 128), blk, 0, s1>>>(
        r16, DMODEL, rnw16, DMODEL, nullptr, nullptr, 0,
        rk16, nullptr, DMODEL, KLEN, DMODEL, DMODEL);
    rbias_k<<<(NHEAD * KLEN) / 256, blk, 0, s1>>>(rrb, rk16, rbias);

    // main stream: input conversions (cat16 fully ready -> evCat)
    cvt_k<<<(MEMLEN * BSZ * DMODEL) / 2048, blk>>>(mems, cat16);
    cvt_k<<<(QLEN * BSZ * DMODEL) / 2048, blk>>>(w, cat16 + (size_t)MEMLEN * BSZ * DMODEL);
    cvt_k<<<(DMODEL * H3) / 2048, blk>>>(qkv_w, qkvw16);
    cudaEventRecord(evCat, 0);

    // main: Q-GEMM (query rows only, N=1024)
    gemm_h<1><<<dim3(DMODEL / 128, (QLEN * BSZ) / 128), blk>>>(
        cat16 + (size_t)MEMLEN * BSZ * DMODEL, DMODEL, qkvw16, H3,
        nullptr, nullptr, 0,
        heads16 + (size_t)MEMLEN * BSZ * H3, nullptr, H3,
        QLEN * BSZ, DMODEL, DMODEL);
    cudaEventRecord(evQ, 0);

    // side: bd16 (needs Q + rk/rbias), then V-GEMM lower half (needs cat16)
    cudaStreamWaitEvent(s1, evQ, 0);
    bd16_gemm<<<dim3(KLEN / 128, QLEN / 128, BSZ * NHEAD), blk, 0, s1>>>(
        qb16, rk16, rbias, BD);
    cudaStreamWaitEvent(s1, evCat, 0);
    gemm_h<1><<<dim3(DMODEL / 128, (KLEN * BSZ / 2) / 128), blk, 0, s1>>>(
        cat16 + halfM * DMODEL, DMODEL, qkvw16 + 2 * DMODEL, H3,
        nullptr, nullptr, 0,
        heads16 + halfM * H3 + 2 * DMODEL, nullptr, H3,
        KLEN * BSZ / 2, DMODEL, DMODEL);
    cudaEventRecord(evJoin, s1);

    // main: K-GEMM (all rows, N=1024), then V-GEMM upper half
    gemm_h<1><<<dim3(DMODEL / 128, (KLEN * BSZ) / 128), blk>>>(
        cat16, DMODEL, qkvw16 + DMODEL, H3, nullptr, nullptr, 0,
        heads16 + DMODEL, nullptr, H3, KLEN * BSZ, DMODEL, DMODEL);
    gemm_h<1><<<dim3(DMODEL / 128, (KLEN * BSZ / 2) / 128), blk>>>(
        cat16, DMODEL, qkvw16 + 2 * DMODEL, H3, nullptr, nullptr, 0,
        heads16 + 2 * DMODEL, nullptr, H3, KLEN * BSZ / 2, DMODEL, DMODEL);

    // ---- join: flash needs BD + full V from side stream ----
    cudaStreamWaitEvent(0, evJoin, 0);

    // flash (64-row tiles, 2 CTAs/SM) -> av16
    flash_k<<<dim3(QLEN / 64, BSZ * NHEAD), dim3(256), FLASH_SMEM>>>(
        heads16, BD, rwb, av16);

    // attn_out = av16 @ ow16 + w
    gemm_h<0><<<dim3(DMODEL / 128, (QLEN * BSZ) / 128), blk>>>(
        av16, DMODEL, ow16, DMODEL, nullptr, w, 0,
        tmp, nullptr, DMODEL, QLEN * BSZ, DMODEL, DMODEL);

    // LN1 (dual fp32 + fp16)
    ln_k<<<QLEN * BSZ, blk>>>(tmp, ln1g, ln1b, out1, out116);

    // ffh16 = relu(out116 @ ffw116 + b1) (fp16 out)
    gemm_h<1><<<dim3(DINNER / 128, (QLEN * BSZ) / 128), blk>>>(
        out116, DMODEL, ffw116, DINNER, ffb1, nullptr, 1,
        ffh16, nullptr, DINNER, QLEN * BSZ, DINNER, DMODEL);

    // tmp = ffh16 @ ffw216 + b2 + out1
    gemm_h<0><<<dim3(DMODEL / 128, (QLEN * BSZ) / 128), blk>>>(
        ffh16, DINNER, ffw216, DMODEL, ffb2, out1, 0,
        tmp, nullptr, DMODEL, QLEN * BSZ, DMODEL, DINNER);

    // LN2 -> output
    ln_k<<<QLEN * BSZ, blk>>>(tmp, ln2g, ln2b, out, nullptr);
}

// round 17
// speedup vs baseline: 1.0189x; 1.0189x over previous
#include <cuda_runtime.h>
#include <cuda_fp16.h>
#include <math.h>
#include <stdint.h>

#define QLEN   1024
#define BSZ    4
#define DMODEL 1024
#define NHEAD  16
#define DHEAD  64
#define DINNER 4096
#define MEMLEN 1024
#define KLEN   2048
#define H3     (3 * DMODEL)   // 3072

// ---- static device scratch (no cudaMalloc allowed) ----
__device__ __half g_heads16[(size_t)KLEN * BSZ * H3];        // fp16 QKV heads
__device__ __half g_rk16[(size_t)KLEN * DMODEL];             // fp16 rk
__device__ float  g_rbias[(size_t)NHEAD * KLEN];
__device__ __half g_BD[(size_t)BSZ * NHEAD * QLEN * KLEN];   // j-indexed BDr
__device__ __half g_av16[(size_t)QLEN * BSZ * DMODEL];
__device__ float  g_tmp[(size_t)QLEN * BSZ * DMODEL];
__device__ float  g_out1[(size_t)QLEN * BSZ * DMODEL];
__device__ __half g_out116[(size_t)QLEN * BSZ * DMODEL];
__device__ __half g_ffh16[(size_t)QLEN * BSZ * DINNER];
__device__ __half g_cat16[(size_t)KLEN * BSZ * DMODEL];
__device__ __half g_r16[(size_t)KLEN * DMODEL];
__device__ __half g_qkvw16[(size_t)DMODEL * H3];
__device__ __half g_rnw16[(size_t)DMODEL * DMODEL];
__device__ __half g_ow16[(size_t)DMODEL * DMODEL];
__device__ __half g_ffw116[(size_t)DMODEL * DINNER];
__device__ __half g_ffw216[(size_t)DINNER * DMODEL];

__device__ __forceinline__ void cpa16(uint32_t s, const void* g) {
    asm volatile("cp.async.cg.shared.global [%0], [%1], 16;" :: "r"(s), "l"(g));
}
#define CP_COMMIT() asm volatile("cp.async.commit_group;")
#define CP_WAIT(N)  asm volatile("cp.async.wait_group %0;" :: "n"(N))

#define MMA_F16(acc, av, bv)                                                \
    asm volatile(                                                           \
        "mma.sync.aligned.m16n8k16.row.col.f32.f16.f16.f32 "                \
        "{%0,%1,%2,%3}, {%4,%5,%6,%7}, {%8,%9}, {%0,%1,%2,%3};"             \
        : "+f"(acc[0]), "+f"(acc[1]), "+f"(acc[2]), "+f"(acc[3])            \
        : "r"(av[0]), "r"(av[1]), "r"(av[2]), "r"(av[3]),                   \
          "r"(bv[0]), "r"(bv[1]))

#define LDSM_X4(r0, r1, r2, r3, addr)                                       \
    asm volatile("ldmatrix.sync.aligned.m8n8.x4.shared.b16 {%0,%1,%2,%3}, [%4];" \
        : "=r"(r0), "=r"(r1), "=r"(r2), "=r"(r3) : "r"(addr))
#define LDSM_X4T(r0, r1, r2, r3, addr)                                      \
    asm volatile("ldmatrix.sync.aligned.m8n8.x4.trans.shared.b16 {%0,%1,%2,%3}, [%4];" \
        : "=r"(r0), "=r"(r1), "=r"(r2), "=r"(r3) : "r"(addr))

// ----------------------------------------------------------------------------
__global__ __launch_bounds__(256) void cvt_k(
    const float* __restrict__ src, __half* __restrict__ dst)
{
    const int i = (blockIdx.x * 256 + threadIdx.x) * 8;
    const float4 a = *(const float4*)(src + i);
    const float4 b = *(const float4*)(src + i + 4);
    __half2 h[4];
    h[0] = __floats2half2_rn(a.x, a.y);
    h[1] = __floats2half2_rn(a.z, a.w);
    h[2] = __floats2half2_rn(b.x, b.y);
    h[3] = __floats2half2_rn(b.z, b.w);
    *(uint4*)(dst + i) = *(uint4*)h;
}

// ----------------------------------------------------------------------------
// Dense fp16 GEMM with separate B/C strides (ldb/ldc, in elements).
// HOUT=0: fp32 out. HOUT=1: fp16 out.
// ----------------------------------------------------------------------------
#define ASTR 40
#define BSTR 136

template <int HOUT>
__global__ __launch_bounds__(256, 2) void gemm_h(
    const __half* __restrict__ A, int lda,
    const __half* __restrict__ B, int ldb,
    const float* __restrict__ bias, const float* __restrict__ resid, int doRelu,
    void* __restrict__ Cv, __half* __restrict__ C16, int ldc,
    int M, int N, int Kd)
{
    __shared__ __half As[3][128 * ASTR];
    __shared__ __half Bs[3][32 * BSTR];

    const int tid  = threadIdx.x;
    const int warp = tid >> 5, lane = tid & 31;
    const int lr = lane >> 2, lc = lane & 3;
    const int bm = blockIdx.y * 128, bn = blockIdx.x * 128;
    const int wm = (warp & 1) * 64;
    const int wn = (warp >> 1) * 32;

    float acc[4][4][4];
#pragma unroll
    for (int mt = 0; mt < 4; mt++)
#pragma unroll
        for (int nt = 0; nt < 4; nt++)
#pragma unroll
            for (int q = 0; q < 4; q++) acc[mt][nt][q] = 0.f;

    const __half* aPtr[2];
    const __half* bPtr[2];
    uint32_t aDst[2], bDst[2];
#pragma unroll
    for (int h = 0; h < 2; h++) {
        const int ch = tid + h * 256;
        const int ar = ch >> 2, ao = (ch & 3) * 8;
        aPtr[h] = A + (long long)(bm + ar) * lda + ao;
        aDst[h] = (uint32_t)__cvta_generic_to_shared(&As[0][ar * ASTR + ao]);
        const int br = ch >> 4, bo = (ch & 15) * 8;
        bPtr[h] = B + (long long)br * ldb + bn + bo;
        bDst[h] = (uint32_t)__cvta_generic_to_shared(&Bs[0][br * BSTR + bo]);
    }
    const long long bStep = (long long)32 * ldb;

    auto load = [&](int kt, int s) {
#pragma unroll
        for (int h = 0; h < 2; h++)
            cpa16(aDst[h] + s * 128 * ASTR * 2, aPtr[h] + kt * 32);
#pragma unroll
        for (int h = 0; h < 2; h++)
            cpa16(bDst[h] + s * 32 * BSTR * 2, bPtr[h] + kt * bStep);
    };

    const int aRow = lane & 15;
    const int selOff = (lane >> 4) << 3;
    const uint32_t asBase = (uint32_t)__cvta_generic_to_shared(&As[0][0]);
    const uint32_t bsBase = (uint32_t)__cvta_generic_to_shared(&Bs[0][0]);

    const int nk = Kd >> 5;
    load(0, 0); CP_COMMIT();
    load(1, 1); CP_COMMIT();

    for (int kt = 0; kt < nk; kt++) {
        const int s = kt % 3;
        CP_WAIT(1);
        __syncthreads();
        if (kt + 2 < nk) load(kt + 2, (kt + 2) % 3);
        CP_COMMIT();

        const uint32_t aS = asBase + (uint32_t)(s * 128 * ASTR * 2);
        const uint32_t bS = bsBase + (uint32_t)(s * 32 * BSTR * 2);
#pragma unroll
        for (int kk = 0; kk < 32; kk += 16) {
            uint32_t af[4][4], bf[4][2];
#pragma unroll
            for (int mt = 0; mt < 4; mt++) {
                const uint32_t addr = aS +
                    (uint32_t)(((wm + mt * 16 + aRow) * ASTR + kk + selOff) * 2);
                LDSM_X4(af[mt][0], af[mt][1], af[mt][2], af[mt][3], addr);
            }
#pragma unroll
            for (int ntp = 0; ntp < 2; ntp++) {
                const uint32_t addr = bS +
                    (uint32_t)(((kk + aRow) * BSTR + wn + ntp * 16 + selOff) * 2);
                LDSM_X4T(bf[2 * ntp][0], bf[2 * ntp][1],
                         bf[2 * ntp + 1][0], bf[2 * ntp + 1][1], addr);
            }
#pragma unroll
            for (int mt = 0; mt < 4; mt++)
#pragma unroll
                for (int nt = 0; nt < 4; nt++)
                    MMA_F16(acc[mt][nt], af[mt], bf[nt]);
        }
    }

#pragma unroll
    for (int mt = 0; mt < 4; mt++) {
#pragma unroll
        for (int nt = 0; nt < 4; nt++) {
            const int col = bn + wn + nt * 8 + lc * 2;
#pragma unroll
            for (int half = 0; half < 2; half++) {
                const int row = bm + wm + mt * 16 + lr + half * 8;
                float v0 = acc[mt][nt][half * 2 + 0];
                float v1 = acc[mt][nt][half * 2 + 1];
                if (bias) { v0 += bias[col]; v1 += bias[col + 1]; }
                if (resid) {
                    const float* rp = resid + (long long)row * ldc + col;
                    v0 += rp[0]; v1 += rp[1];
                }
                if (doRelu) { v0 = fmaxf(v0, 0.f); v1 = fmaxf(v1, 0.f); }
                if (HOUT == 1) {
                    *(__half2*)((__half*)Cv + (long long)row * ldc + col) =
                        __floats2half2_rn(v0, v1);
                } else {
                    float* cp = (float*)Cv + (long long)row * ldc + col;
                    cp[0] = v0; cp[1] = v1;
                }
            }
        }
    }
}

// ----------------------------------------------------------------------------
// rbias[n][c] = rrb_n . rk16_c  (fp32 accumulate over fp16 rk)
// ----------------------------------------------------------------------------
__global__ __launch_bounds__(256) void rbias_k(
    const float* __restrict__ rrb, const __half* __restrict__ rk16,
    float* __restrict__ rbias)
{
    const int idx = blockIdx.x * 256 + threadIdx.x;
    const int c = idx >> 4, n = idx & 15;
    const __half2* rp = (const __half2*)(rk16 + (size_t)c * DMODEL + n * DHEAD);
    const float* bp = rrb + n * DHEAD;
    float s = 0.f;
#pragma unroll
    for (int d = 0; d < 32; d++) {
        const float2 rv = __half22float2(rp[d]);
        s += rv.x * bp[2 * d] + rv.y * bp[2 * d + 1];
    }
    rbias[n * KLEN + c] = s;
}

// ----------------------------------------------------------------------------
// BD GEMM fp16, j-indexed output: BDr[bn][i][j] = q_i . rk_{j-i+1023} + rbias.
// ----------------------------------------------------------------------------
#define BDSTR 72

__global__ __launch_bounds__(256, 2) void bd16_gemm(
    const __half* __restrict__ Q16,
    const __half* __restrict__ RK16,
    const float* __restrict__ rbias, __half* __restrict__ BD)
{
    __shared__ __half As[128 * BDSTR];
    __shared__ __half Bs[128 * BDSTR];

    const int tid = threadIdx.x;
    const int warp = tid >> 5, lane = tid & 31;
    const int lr = lane >> 2, lc = lane & 3;
    const int bm = blockIdx.y * 128, bn = blockIdx.x * 128;
    if (bm + bn < 769) return;   // whole tile lands at j < 0, never read
    const int bnidx = blockIdx.z;
    const int b = bnidx >> 4, n = bnidx & 15;
    const int wm = (warp & 1) * 64;
    const int wn = (warp >> 1) * 32;
    const int aRow = lane & 15;
    const int selOff = (lane >> 4) << 3;
    const uint32_t as_b = (uint32_t)__cvta_generic_to_shared(As);
    const uint32_t bs_b = (uint32_t)__cvta_generic_to_shared(Bs);

#pragma unroll
    for (int h = 0; h < 4; h++) {
        const int ch = tid + h * 256;
        const int row = ch >> 3, seg = (ch & 7) * 8;
        const __half* ga = Q16 + ((size_t)(bm + row) * BSZ + b) * H3 + n * DHEAD + seg;
        cpa16(as_b + (uint32_t)((row * BDSTR + seg) << 1), ga);
    }
#pragma unroll
    for (int h = 0; h < 4; h++) {
        const int ch = tid + h * 256;
        const int row = ch >> 3, seg = (ch & 7) * 8;
        const __half* gb = RK16 + (size_t)(bn + row) * DMODEL + n * DHEAD + seg;
        cpa16(bs_b + (uint32_t)((row * BDSTR + seg) << 1), gb);
    }
    CP_COMMIT();

    float acc[4][4][4];
#pragma unroll
    for (int mt = 0; mt < 4; mt++)
#pragma unroll
        for (int nt = 0; nt < 4; nt++)
#pragma unroll
            for (int q = 0; q < 4; q++) acc[mt][nt][q] = 0.f;

    CP_WAIT(0);
    __syncthreads();

#pragma unroll
    for (int kk = 0; kk < 64; kk += 16) {
        uint32_t af[4][4], bfr[4][2];
#pragma unroll
        for (int mt = 0; mt < 4; mt++) {
            const uint32_t addr = as_b +
                (uint32_t)(((wm + mt * 16 + aRow) * BDSTR + kk + selOff) << 1);
            LDSM_X4(af[mt][0], af[mt][1], af[mt][2], af[mt][3], addr);
        }
#pragma unroll
        for (int p = 0; p < 2; p++) {
            uint32_t r0, r1, r2, r3;
            const uint32_t addr = bs_b +
                (uint32_t)(((wn + p * 16 + aRow) * BDSTR + kk + selOff) << 1);
            LDSM_X4(r0, r1, r2, r3, addr);
            bfr[2 * p][0] = r0; bfr[2 * p][1] = r2;
            bfr[2 * p + 1][0] = r1; bfr[2 * p + 1][1] = r3;
        }
#pragma unroll
        for (int mt = 0; mt < 4; mt++)
#pragma unroll
            for (int nt = 0; nt < 4; nt++)
                MMA_F16(acc[mt][nt], af[mt], bfr[nt]);
    }

    // epilogue: + rbias, rel-shifted fp16 store (j = c + i - 1023)
#pragma unroll
    for (int mt = 0; mt < 4; mt++) {
#pragma unroll
        for (int nt = 0; nt < 4; nt++) {
            const int col = bn + wn + nt * 8 + lc * 2;
            const float rb0 = rbias[n * KLEN + col];
            const float rb1 = rbias[n * KLEN + col + 1];
#pragma unroll
            for (int half = 0; half < 2; half++) {
                const int row = bm + wm + mt * 16 + lr + half * 8;
                const float v0 = acc[mt][nt][half * 2 + 0] + rb0;
                const float v1 = acc[mt][nt][half * 2 + 1] + rb1;
                __half* rowp = BD + ((size_t)bnidx * QLEN + row) * KLEN;
                const int j = col + row - (QLEN - 1);
                if (j >= 0)     rowp[j]     = __float2half_rn(v0);
                if (j + 1 >= 0) rowp[j + 1] = __float2half_rn(v1);
            }
        }
    }
}

// ----------------------------------------------------------------------------
// Flash attention v7: 64-row q-tiles, 256 threads, 2 CTAs/SM. Independent
// per-col-half online softmax (split-KV) -> only 2 barriers per j-tile;
// halves merged once at the end.
// ----------------------------------------------------------------------------
#define KSTR  72
#define BDF   136
#define OSTR  72
#define FLASH_SMEM (64*KSTR*2 /*Q*/ + 2*128*KSTR*2 /*K*/ + 128*KSTR*2 /*V*/ \
                    + 64*BDF*2 /*Bd*/ + 2*64*4 /*mArr+lArr*/)

__global__ __launch_bounds__(256, 2) void flash_k(
    const __half* __restrict__ heads16,
    const __half* __restrict__ BD,
    const float* __restrict__ rwb, __half* __restrict__ av16)
{
    extern __shared__ char smc[];
    __half* Qs16 = (__half*)smc;
    __half* Ks16 = Qs16 + 64 * KSTR;              // 2*128*72 (reused as Osum)
    __half* Vs16 = Ks16 + 2 * 128 * KSTR;
    __half* Bds  = Vs16 + 128 * KSTR;
    float*  mArr = (float*)(Bds + 64 * BDF);      // [64] (half-1 row max)
    float*  lArr = mArr + 64;                     // [64] (half-1 row sum)
    float*  Osum = (float*)Ks16;                  // 64*72 floats
    const uint32_t qs_b = (uint32_t)__cvta_generic_to_shared(Qs16);
    const uint32_t ks_b = (uint32_t)__cvta_generic_to_shared(Ks16);
    const uint32_t vs_b = (uint32_t)__cvta_generic_to_shared(Vs16);
    const uint32_t bd_b = (uint32_t)__cvta_generic_to_shared(Bds);

    const int tid = threadIdx.x;
    const int warp = tid >> 5, lane = tid & 31;
    const int lr = lane >> 2, lc = lane & 3;
    const int aRow = lane & 15;
    const int selOff = (lane >> 4) << 3;
    const int qt = (int)gridDim.x - 1 - (int)blockIdx.x;   // longest-first
    const int i0 = qt * 64;
    const int bn = blockIdx.y;
    const int b = bn >> 4, n = bn & 15;
    const int rg  = warp & 3;
    const int chh = warp >> 2;
    const int wm  = rg * 16;
    const int njt = ((i0 + 63 + MEMLEN) >> 7) + 1;

    auto loadK = [&](int jt, int buf) {
        const int j0 = jt * 128;
#pragma unroll
        for (int it = 0; it < 4; it++) {
            const int c = tid + it * 256;
            const int row = c >> 3, seg = (c & 7) << 3;
            const __half* g = heads16 + ((size_t)(j0 + row) * BSZ + b) * H3 + DMODEL + n * DHEAD + seg;
            cpa16(ks_b + (uint32_t)((((buf << 7) + row) * KSTR + seg) << 1), g);
        }
    };
    auto loadV = [&](int jt) {
        const int j0 = jt * 128;
#pragma unroll
        for (int it = 0; it < 4; it++) {
            const int c = tid + it * 256;
            const int row = c >> 3, seg = (c & 7) << 3;
            const __half* g = heads16 + ((size_t)(j0 + row) * BSZ + b) * H3 + 2 * DMODEL + n * DHEAD + seg;
            cpa16(vs_b + (uint32_t)((row * KSTR + seg) << 1), g);
        }
    };
    auto loadBd = [&](int jt) {
        const int j0 = jt * 128;
#pragma unroll
        for (int it = 0; it < 4; it++) {
            const int c = tid + it * 256;
            const int row = c >> 4, seg = (c & 15) << 3;
            const __half* g = BD + ((size_t)bn * QLEN + i0 + row) * KLEN + j0 + seg;
            cpa16(bd_b + (uint32_t)((row * BDF + seg) << 1), g);
        }
    };

    loadK(0, 0); CP_COMMIT();
    const __half* qb16 = heads16 + (size_t)MEMLEN * BSZ * H3;
#pragma unroll
    for (int it = 0; it < 4; it++) {
        const int idx = tid + it * 256;
        const int row = idx >> 4, c4 = (idx & 15) * 4;
        const __half2* qp = (const __half2*)(qb16 + ((size_t)(i0 + row) * BSZ + b) * H3 + n * DHEAD + c4);
        const float2 q0 = __half22float2(qp[0]);
        const float2 q1 = __half22float2(qp[1]);
        const float4 bb = *(const float4*)(rwb + n * DHEAD + c4);
        *(__half2*)(Qs16 + row * KSTR + c4)     = __floats2half2_rn(q0.x + bb.x, q0.y + bb.y);
        *(__half2*)(Qs16 + row * KSTR + c4 + 2) = __floats2half2_rn(q1.x + bb.z, q1.y + bb.w);
    }

    // per-half online softmax state (rows wm+lr, wm+lr+8)
    float m0 = -1e30f, m1 = -1e30f, l0 = 0.f, l1 = 0.f;

    float accO[8][4];
#pragma unroll
    for (int nt = 0; nt < 8; nt++)
#pragma unroll
        for (int q = 0; q < 4; q++) accO[nt][q] = 0.f;

    CP_WAIT(0);
    __syncthreads();

    for (int jt = 0; jt < njt; jt++) {
        const int j0 = jt * 128;
        const int cur = jt & 1;
        const bool more = (jt + 1 < njt);

        loadV(jt); loadBd(jt); CP_COMMIT();
        if (more) { loadK(jt + 1, cur ^ 1); CP_COMMIT(); }

        float accS[8][4];
#pragma unroll
        for (int nt = 0; nt < 8; nt++)
#pragma unroll
            for (int q = 0; q < 4; q++) accS[nt][q] = 0.f;

#pragma unroll
        for (int kk = 0; kk < 64; kk += 16) {
            uint32_t af[4], bfr[8][2];
            {
                const uint32_t addr = qs_b +
                    (uint32_t)(((wm + aRow) * KSTR + kk + selOff) << 1);
                LDSM_X4(af[0], af[1], af[2], af[3], addr);
            }
#pragma unroll
            for (int p = 0; p < 4; p++) {
                uint32_t r0, r1, r2, r3;
                const uint32_t addr = ks_b +
                    (uint32_t)((((cur << 7) + chh * 64 + p * 16 + aRow) * KSTR + kk + selOff) << 1);
                LDSM_X4(r0, r1, r2, r3, addr);
                bfr[2 * p][0] = r0; bfr[2 * p][1] = r2;
                bfr[2 * p + 1][0] = r1; bfr[2 * p + 1][1] = r3;
            }
#pragma unroll
            for (int nt = 0; nt < 8; nt++)
                MMA_F16(accS[nt], af, bfr[nt]);
        }

        if (more) { CP_WAIT(1); } else { CP_WAIT(0); }
        __syncthreads();   // Bd/V visible

        // add BD + mask + scale; per-half row max (no cross-half exchange)
        const int dcol = j0 + chh * 64 - (i0 + wm);
        const int lim0 = lr + MEMLEN - dcol;
        const int lim1 = lim0 + 8;
        float mx0 = -1e30f, mx1 = -1e30f;
#pragma unroll
        for (int nt = 0; nt < 8; nt++) {
            const int cl = nt * 8 + 2 * lc;
            const float2 b0 = __half22float2(*(const __half2*)&Bds[(wm + lr) * BDF + chh * 64 + nt * 8 + 2 * lc]);
            const float2 b1 = __half22float2(*(const __half2*)&Bds[(wm + lr + 8) * BDF + chh * 64 + nt * 8 + 2 * lc]);
            accS[nt][0] = (cl     <= lim0) ? (accS[nt][0] + b0.x) * 0.125f : -1e30f;
            accS[nt][1] = (cl + 1 <= lim0) ? (accS[nt][1] + b0.y) * 0.125f : -1e30f;
            accS[nt][2] = (cl     <= lim1) ? (accS[nt][2] + b1.x) * 0.125f : -1e30f;
            accS[nt][3] = (cl + 1 <= lim1) ? (accS[nt][3] + b1.y) * 0.125f : -1e30f;
            mx0 = fmaxf(mx0, fmaxf(accS[nt][0], accS[nt][1]));
            mx1 = fmaxf(mx1, fmaxf(accS[nt][2], accS[nt][3]));
        }
#pragma unroll
        for (int o = 1; o <= 2; o <<= 1) {
            mx0 = fmaxf(mx0, __shfl_xor_sync(0xffffffffu, mx0, o));
            mx1 = fmaxf(mx1, __shfl_xor_sync(0xffffffffu, mx1, o));
        }
        const float nm0 = fmaxf(m0, mx0);
        const float nm1 = fmaxf(m1, mx1);

        uint32_t pLo[8], pHi[8];
        float ls0 = 0.f, ls1 = 0.f;
#pragma unroll
        for (int nt = 0; nt < 8; nt++) {
            const __half2 h0 = __floats2half2_rn(__expf(accS[nt][0] - nm0),
                                                 __expf(accS[nt][1] - nm0));
            const __half2 h1 = __floats2half2_rn(__expf(accS[nt][2] - nm1),
                                                 __expf(accS[nt][3] - nm1));
            pLo[nt] = *(const uint32_t*)&h0;
            pHi[nt] = *(const uint32_t*)&h1;
            const float2 f0 = __half22float2(h0);
            const float2 f1 = __half22float2(h1);
            ls0 += f0.x + f0.y;
            ls1 += f1.x + f1.y;
        }
#pragma unroll
        for (int o = 1; o <= 2; o <<= 1) {
            ls0 += __shfl_xor_sync(0xffffffffu, ls0, o);
            ls1 += __shfl_xor_sync(0xffffffffu, ls1, o);
        }
        const float a0 = __expf(m0 - nm0);
        const float a1 = __expf(m1 - nm1);
        m0 = nm0; m1 = nm1;
        l0 = l0 * a0 + ls0;
        l1 = l1 * a1 + ls1;

#pragma unroll
        for (int nt = 0; nt < 8; nt++) {
            accO[nt][0] *= a0; accO[nt][1] *= a0;
            accO[nt][2] *= a1; accO[nt][3] *= a1;
        }
#pragma unroll
        for (int p = 0; p < 4; p++) {
            uint32_t af[4];
            af[0] = pLo[2 * p];     af[1] = pHi[2 * p];
            af[2] = pLo[2 * p + 1]; af[3] = pHi[2 * p + 1];
            uint32_t bf[8][2];
#pragma unroll
            for (int nb = 0; nb < 4; nb++) {
                const uint32_t addr = vs_b +
                    (uint32_t)(((chh * 64 + p * 16 + aRow) * KSTR + nb * 16 + selOff) << 1);
                LDSM_X4T(bf[2 * nb][0], bf[2 * nb][1],
                         bf[2 * nb + 1][0], bf[2 * nb + 1][1], addr);
            }
#pragma unroll
            for (int nt = 0; nt < 8; nt++)
                MMA_F16(accO[nt], af, bf[nt]);
        }

        if (more) CP_WAIT(0);
        __syncthreads();   // Vs/Bds reads done + K(jt+1) resident
    }

    // ---- merge the two col-halves (split-KV combine), write av16 ----
    if (chh == 1) {
        if (lc == 0) {
            mArr[wm + lr] = m0;      lArr[wm + lr] = l0;
            mArr[wm + lr + 8] = m1;  lArr[wm + lr + 8] = l1;
        }
#pragma unroll
        for (int nt = 0; nt < 8; nt++) {
            const int col = nt * 8 + 2 * lc;
            *(float2*)&Osum[(wm + lr) * OSTR + col] =
                make_float2(accO[nt][0], accO[nt][1]);
            *(float2*)&Osum[(wm + lr + 8) * OSTR + col] =
                make_float2(accO[nt][2], accO[nt][3]);
        }
    }
    __syncthreads();
    if (chh == 0) {
        const float mo0 = mArr[wm + lr],     lo0 = lArr[wm + lr];
        const float mo1 = mArr[wm + lr + 8], lo1 = lArr[wm + lr + 8];
        const float mt0 = fmaxf(m0, mo0);
        const float mt1 = fmaxf(m1, mo1);
        const float as0 = __expf(m0 - mt0), ao0 = __expf(mo0 - mt0);
        const float as1 = __expf(m1 - mt1), ao1 = __expf(mo1 - mt1);
        const float inv0 = 1.f / (l0 * as0 + lo0 * ao0);
        const float inv1 = 1.f / (l1 * as1 + lo1 * ao1);
#pragma unroll
        for (int nt = 0; nt < 8; nt++) {
            const int col = nt * 8 + 2 * lc;
            const float2 s0 = *(const float2*)&Osum[(wm + lr) * OSTR + col];
            const float2 s1 = *(const float2*)&Osum[(wm + lr + 8) * OSTR + col];
            __half2* p0 = (__half2*)(av16 + ((size_t)(i0 + wm + lr) * BSZ + b) * DMODEL + n * DHEAD + col);
            *p0 = __floats2half2_rn((accO[nt][0] * as0 + s0.x * ao0) * inv0,
                                    (accO[nt][1] * as0 + s0.y * ao0) * inv0);
            __half2* p1 = (__half2*)(av16 + ((size_t)(i0 + wm + lr + 8) * BSZ + b) * DMODEL + n * DHEAD + col);
            *p1 = __floats2half2_rn((accO[nt][2] * as1 + s1.x * ao1) * inv1,
                                    (accO[nt][3] * as1 + s1.y * ao1) * inv1);
        }
    }
}

// ----------------------------------------------------------------------------
__device__ __forceinline__ float warpSum(float v) {
#pragma unroll
    for (int o = 16; o; o >>= 1) v += __shfl_xor_sync(0xffffffffu, v, o);
    return v;
}

__global__ __launch_bounds__(256) void ln_k(
    const float* __restrict__ X, const float* __restrict__ gam,
    const float* __restrict__ bet, float* __restrict__ Y,
    __half* __restrict__ Y16)
{
    __shared__ float red[8];
    const size_t row = blockIdx.x;
    const int tid = threadIdx.x;
    const float4 v = *(const float4*)(X + row * DMODEL + tid * 4);
    float s = v.x + v.y + v.z + v.w;
    float q = v.x * v.x + v.y * v.y + v.z * v.z + v.w * v.w;

    float ws = warpSum(s);
    if ((tid & 31) == 0) red[tid >> 5] = ws;
    __syncthreads();
    if (tid < 32) {
        float t = (tid < 8) ? red[tid] : 0.f;
        t = warpSum(t);
        if (tid == 0) red[0] = t;
    }
    __syncthreads();
    const float mu = red[0] * (1.f / DMODEL);
    __syncthreads();

    float wq = warpSum(q);
    if ((tid & 31) == 0) red[tid >> 5] = wq;
    __syncthreads();
    if (tid < 32) {
        float t = (tid < 8) ? red[tid] : 0.f;
        t = warpSum(t);
        if (tid == 0) red[0] = t;
    }
    __syncthreads();
    const float var = red[0] * (1.f / DMODEL) - mu * mu;
    const float rs = rsqrtf(var + 1e-5f);

    const float4 gv = *(const float4*)(gam + tid * 4);
    const float4 bv = *(const float4*)(bet + tid * 4);
    float4 o;
    o.x = (v.x - mu) * rs * gv.x + bv.x;
    o.y = (v.y - mu) * rs * gv.y + bv.y;
    o.z = (v.z - mu) * rs * gv.z + bv.z;
    o.w = (v.w - mu) * rs * gv.w + bv.w;
    *(float4*)(Y + row * DMODEL + tid * 4) = o;
    if (Y16) {
        __half2 h[2] = { __floats2half2_rn(o.x, o.y), __floats2half2_rn(o.z, o.w) };
        *(uint2*)(Y16 + row * DMODEL + tid * 4) = *(uint2*)h;
    }
}

// ----------------------------------------------------------------------------
extern "C" void kernel_launch(void* const* d_in, const int* in_sizes, int n_in,
                              void* d_out, int out_size)
{
    (void)in_sizes; (void)n_in; (void)out_size;
    const float* w       = (const float*)d_in[0];
    const float* r       = (const float*)d_in[1];
    const float* mems    = (const float*)d_in[2];
    const float* qkv_w   = (const float*)d_in[3];
    const float* r_net_w = (const float*)d_in[4];
    const float* o_w     = (const float*)d_in[5];
    const float* rwb     = (const float*)d_in[6];
    const float* rrb     = (const float*)d_in[7];
    const float* ln1g    = (const float*)d_in[8];
    const float* ln1b    = (const float*)d_in[9];
    const float* ffw1    = (const float*)d_in[10];
    const float* ffb1    = (const float*)d_in[11];
    const float* ffw2    = (const float*)d_in[12];
    const float* ffb2    = (const float*)d_in[13];
    const float* ln2g    = (const float*)d_in[14];
    const float* ln2b    = (const float*)d_in[15];
    float* out = (float*)d_out;

    float *rbias, *tmp, *out1;
    __half *heads16, *rk16, *BD, *av16, *out116, *ffh16;
    __half *cat16, *r16, *qkvw16, *rnw16, *ow16, *ffw116, *ffw216;
    cudaGetSymbolAddress((void**)&heads16, g_heads16);
    cudaGetSymbolAddress((void**)&rk16,    g_rk16);
    cudaGetSymbolAddress((void**)&rbias,   g_rbias);
    cudaGetSymbolAddress((void**)&BD,      g_BD);
    cudaGetSymbolAddress((void**)&av16,    g_av16);
    cudaGetSymbolAddress((void**)&tmp,     g_tmp);
    cudaGetSymbolAddress((void**)&out1,    g_out1);
    cudaGetSymbolAddress((void**)&out116,  g_out116);
    cudaGetSymbolAddress((void**)&ffh16,   g_ffh16);
    cudaGetSymbolAddress((void**)&cat16,   g_cat16);
    cudaGetSymbolAddress((void**)&r16,     g_r16);
    cudaGetSymbolAddress((void**)&qkvw16,  g_qkvw16);
    cudaGetSymbolAddress((void**)&rnw16,   g_rnw16);
    cudaGetSymbolAddress((void**)&ow16,    g_ow16);
    cudaGetSymbolAddress((void**)&ffw116,  g_ffw116);
    cudaGetSymbolAddress((void**)&ffw216,  g_ffw216);

    static cudaStream_t s1 = nullptr;
    static cudaEvent_t evFork = nullptr, evQ = nullptr, evJoin = nullptr;
    static int s_init_done = 0;
    if (!s_init_done) {
        cudaFuncSetAttribute(flash_k, cudaFuncAttributeMaxDynamicSharedMemorySize,
                             FLASH_SMEM);
        cudaStreamCreateWithFlags(&s1, cudaStreamNonBlocking);
        cudaEventCreateWithFlags(&evFork, cudaEventDisableTiming);
        cudaEventCreateWithFlags(&evQ, cudaEventDisableTiming);
        cudaEventCreateWithFlags(&evJoin, cudaEventDisableTiming);
        s_init_done = 1;
    }

    const dim3 blk(256);
    const __half* qb16 = heads16 + (size_t)MEMLEN * BSZ * H3;  // query rows

    // ---- fork side stream (R15 schedule, proven) ----
    cudaEventRecord(evFork, 0);
    cudaStreamWaitEvent(s1, evFork, 0);

    // side stream: r/weight conversions -> rk GEMM -> rbias
    cvt_k<<<(KLEN * DMODEL) / 2048, blk, 0, s1>>>(r, r16);
    cvt_k<<<(DMODEL * DMODEL) / 2048, blk, 0, s1>>>(r_net_w, rnw16);
    cvt_k<<<(DMODEL * DMODEL) / 2048, blk, 0, s1>>>(o_w, ow16);
    cvt_k<<<(DMODEL * DINNER) / 2048, blk, 0, s1>>>(ffw1, ffw116);
    cvt_k<<<(DINNER * DMODEL) / 2048, blk, 0, s1>>>(ffw2, ffw216);
    gemm_h<1><<<dim3(DMODEL / 128, KLEN / 128), blk, 0, s1>>>(
        r16, DMODEL, rnw16, DMODEL, nullptr, nullptr, 0,
        rk16, nullptr, DMODEL, KLEN, DMODEL, DMODEL);
    rbias_k<<<(NHEAD * KLEN) / 256, blk, 0, s1>>>(rrb, rk16, rbias);

    // main stream: input conversions -> Q-GEMM (query rows only, N=1024)
    cvt_k<<<(MEMLEN * BSZ * DMODEL) / 2048, blk>>>(mems, cat16);
    cvt_k<<<(QLEN * BSZ * DMODEL) / 2048, blk>>>(w, cat16 + (size_t)MEMLEN * BSZ * DMODEL);
    cvt_k<<<(DMODEL * H3) / 2048, blk>>>(qkv_w, qkvw16);
    gemm_h<1><<<dim3(DMODEL / 128, (QLEN * BSZ) / 128), blk>>>(
        cat16 + (size_t)MEMLEN * BSZ * DMODEL, DMODEL, qkvw16, H3,
        nullptr, nullptr, 0,
        heads16 + (size_t)MEMLEN * BSZ * H3, nullptr, H3,
        QLEN * BSZ, DMODEL, DMODEL);
    cudaEventRecord(evQ, 0);

    // side stream: bd16 after Q-GEMM + rk/rbias (concurrent with KV-GEMM)
    cudaStreamWaitEvent(s1, evQ, 0);
    bd16_gemm<<<dim3(KLEN / 128, QLEN / 128, BSZ * NHEAD), blk, 0, s1>>>(
        qb16, rk16, rbias, BD);
    cudaEventRecord(evJoin, s1);

    // main stream: KV-GEMM (all rows, N=2048 -> cols 1024..3071 of heads16)
    gemm_h<1><<<dim3((2 * DMODEL) / 128, (KLEN * BSZ) / 128), blk>>>(
        cat16, DMODEL, qkvw16 + DMODEL, H3, nullptr, nullptr, 0,
        heads16 + DMODEL, nullptr, H3, KLEN * BSZ, 2 * DMODEL, DMODEL);

    // ---- join: flash needs BD from side stream ----
    cudaStreamWaitEvent(0, evJoin, 0);

    // flash (64-row tiles, 2 CTAs/SM, split-KV softmax) -> av16
    flash_k<<<dim3(QLEN / 64, BSZ * NHEAD), dim3(256), FLASH_SMEM>>>(
        heads16, BD, rwb, av16);

    // attn_out = av16 @ ow16 + w
    gemm_h<0><<<dim3(DMODEL / 128, (QLEN * BSZ) / 128), blk>>>(
        av16, DMODEL, ow16, DMODEL, nullptr, w, 0,
        tmp, nullptr, DMODEL, QLEN * BSZ, DMODEL, DMODEL);

    // LN1 (dual fp32 + fp16)
    ln_k<<<QLEN * BSZ, blk>>>(tmp, ln1g, ln1b, out1, out116);

    // ffh16 = relu(out116 @ ffw116 + b1) (fp16 out)
    gemm_h<1><<<dim3(DINNER / 128, (QLEN * BSZ) / 128), blk>>>(
        out116, DMODEL, ffw116, DINNER, ffb1, nullptr, 1,
        ffh16, nullptr, DINNER, QLEN * BSZ, DINNER, DMODEL);

    // tmp = ffh16 @ ffw216 + b2 + out1
    gemm_h<0><<<dim3(DMODEL / 128, (QLEN * BSZ) / 128), blk>>>(
        ffh16, DINNER, ffw216, DMODEL, ffb2, out1, 0,
        tmp, nullptr, DMODEL, QLEN * BSZ, DMODEL, DINNER);

    // LN2 -> output
    ln_k<<<QLEN * BSZ, blk>>>(tmp, ln2g, ln2b, out, nullptr);
}